// round 8
// baseline (speedup 1.0000x reference)
#include <cuda_runtime.h>
#include <math.h>

#define T_TOK 4096
#define NH 1024          // hidden
#define NI 512           // intermediate
#define NE 16            // real experts
#define NSLOT 32         // real + zero slots
#define TOPK 4
#define MAXP 4096        // max pairs per expert (<= T)

// GEMM tiling (R5 config: block 128x64, 8 warps as 4m x 2n, warp tile 32x32)
#define BM 128
#define BN 64
#define BK 16

// ---- static device scratch (no runtime allocation allowed) ----
__device__ int   g_cnt[NE];                       // pairs per expert
__device__ int   g_tok[NE * MAXP];                // token index per pair slot
__device__ float g_wt [NE * MAXP];                // routing weight per pair slot
__device__ int   g_tk_n[T_TOK];                   // real experts chosen per token
__device__ int   g_tk_pair[T_TOK * TOPK];         // pair indices per token (topk order)
__device__ float g_act [(size_t)NE * MAXP * NI];  // SwiGLU activations
__device__ float g_pout[(size_t)NE * MAXP * NH];  // per-pair down output

// ---------------------------------------------------------------------------
__device__ __forceinline__ unsigned f2tf(float f) {
    unsigned r;
    asm("cvt.rna.tf32.f32 %0, %1;" : "=r"(r) : "f"(f));
    return r;
}

__device__ __forceinline__ void mma_tf32(float* d, const uint4& a, const uint2& b) {
    asm volatile(
        "mma.sync.aligned.m16n8k8.row.col.f32.tf32.tf32.f32 "
        "{%0,%1,%2,%3}, {%4,%5,%6,%7}, {%8,%9}, {%0,%1,%2,%3};"
        : "+f"(d[0]), "+f"(d[1]), "+f"(d[2]), "+f"(d[3])
        : "r"(a.x), "r"(a.y), "r"(a.z), "r"(a.w), "r"(b.x), "r"(b.y));
}

// ---------------------------------------------------------------------------
__global__ void reset_kernel() {
    int i = threadIdx.x;
    if (i < NE) g_cnt[i] = 0;
}

// ---------------------------------------------------------------------------
// Router: one block (256 threads) per token.
__global__ void router_kernel(const float* __restrict__ x,
                              const float* __restrict__ rw,
                              const float* __restrict__ bias,
                              float* __restrict__ out) {
    int t = blockIdx.x;
    __shared__ float sc[NSLOT];
    __shared__ float s_zero;
    int tid  = threadIdx.x;           // 256
    int slot = tid >> 3;              // 32 slots, 8 threads each
    int sub  = tid & 7;
    const float* xr = x  + (size_t)t * NH;
    const float* wr = rw + (size_t)slot * NH;

    float acc = 0.f;
    for (int h = sub * 4; h < NH; h += 32) {
        float4 xv = *reinterpret_cast<const float4*>(xr + h);
        float4 wv = *reinterpret_cast<const float4*>(wr + h);
        acc += xv.x * wv.x + xv.y * wv.y + xv.z * wv.z + xv.w * wv.w;
    }
    acc += __shfl_down_sync(0xffffffffu, acc, 4, 8);
    acc += __shfl_down_sync(0xffffffffu, acc, 2, 8);
    acc += __shfl_down_sync(0xffffffffu, acc, 1, 8);
    if (sub == 0) sc[slot] = acc;
    __syncthreads();

    if (tid == 0) {
        float mx = -1e30f;
        for (int i = 0; i < NSLOT; i++) mx = fmaxf(mx, sc[i]);
        float e[NSLOT], sum = 0.f;
        for (int i = 0; i < NSLOT; i++) { e[i] = expf(sc[i] - mx); sum += e[i]; }
        float inv = 1.f / sum;
        float sb[NSLOT];
        for (int i = 0; i < NSLOT; i++) {
            sc[i] = e[i] * inv;            // raw score (weight source)
            sb[i] = sc[i] + bias[i];       // selection score
        }
        float zero_w = 0.f;
        int tkn = 0;
        for (int kk = 0; kk < TOPK; kk++) {
            int bi = 0; float bv = -1e30f;
            for (int i = 0; i < NSLOT; i++)
                if (sb[i] > bv) { bv = sb[i]; bi = i; }
            sb[bi] = -1e30f;
            float w = sc[bi];
            if (bi < NE) {
                int s2 = atomicAdd(&g_cnt[bi], 1);
                g_tok[bi * MAXP + s2] = t;
                g_wt [bi * MAXP + s2] = w;
                g_tk_pair[t * TOPK + tkn] = bi * MAXP + s2;
                tkn++;
            } else {
                zero_w += w;
            }
        }
        g_tk_n[t] = tkn;
        s_zero = zero_w;
    }
    __syncthreads();

    float zw = s_zero;
    for (int h = tid; h < NH; h += 256)
        out[(size_t)t * NH + h] = zw * xr[h];
}

// ---------------------------------------------------------------------------
// GEMM1 (tf32 TC, depth-2 A prefetch / depth-1 B, double-buffered smem):
// act = silu(X.Wg)*(X.Wu).  Block 128x64, 8 warps (4m x 2n), warp tile 32x32.
#define SA_BUF (8 * 32 * 4 * 2)   // per-buffer unsigned count for A  (k8=2)
#define SB_BUF (8 * 32 * 2 * 2)   // per-buffer unsigned count for B  (k8=2)

__global__ __launch_bounds__(256) void gemm1_tc(const float* __restrict__ x,
                                                const float* __restrict__ wg,
                                                const float* __restrict__ wu) {
    int e    = blockIdx.z;
    int cnt  = g_cnt[e];
    int row0 = blockIdx.y * BM;
    if (row0 >= cnt) return;
    int col0 = blockIdx.x * BN;

    __shared__ unsigned sA [2 * SA_BUF];   // 16KB
    __shared__ unsigned sBg[2 * SB_BUF];   // 8KB
    __shared__ unsigned sBu[2 * SB_BUF];   // 8KB

    int tid  = threadIdx.x;
    int lane = tid & 31;
    int wid  = tid >> 5;
    int wm   = wid >> 1;      // 0..3
    int wn   = wid & 1;       // 0..1

    // --- A loader precompute: 2 float4 per thread ---
    int tok[2];
    unsigned abase[2];
    int ac[2];
#pragma unroll
    for (int it = 0; it < 2; it++) {
        int f = tid + 256 * it;
        int r = f >> 2;
        int c = (f & 3) * 4;
        ac[it] = c;
        int rr = row0 + r;
        tok[it] = (rr < cnt) ? g_tok[e * MAXP + rr] : -1;
        int k8  = c >> 3;
        int reg = ((r >> 3) & 1) + 2 * ((c >> 2) & 1);
        abase[it] = (((unsigned)k8 * 8 + (r >> 4)) * 32 + (r & 7) * 4) * 4 + reg;
    }
    // --- B loader precompute ---
    int bkr = tid >> 4;             // 0..15 (k row within tile)
    int bc  = (tid & 15) * 4;       // 0..60 (col)
    const float* wgB = wg + (size_t)e * NH * NI + (size_t)bkr * NI + col0 + bc;
    const float* wuB = wu + (size_t)e * NH * NI + (size_t)bkr * NI + col0 + bc;
    int bk8  = bkr >> 3;
    int bkk  = bkr & 7;
    int breg = bkk >> 2;
    int bt   = bkk & 3;
    int bnt  = bc >> 3;
    unsigned bbase = (((unsigned)bk8 * 8 + bnt) * 32 + (bc & 7) * 4 + bt) * 2 + breg;

    float dg[2][4][4] = {};
    float du[2][4][4] = {};

    // prefetch registers: A has two sets (depth-2); B one set (depth-1)
    float4 pAs[2][2];
    float4 pG, pU;

    // --- prologue: stage tile 0 directly ---
    {
        float4 a0[2];
#pragma unroll
        for (int it = 0; it < 2; it++) {
            a0[it] = make_float4(0.f, 0.f, 0.f, 0.f);
            if (tok[it] >= 0)
                a0[it] = *reinterpret_cast<const float4*>(x + (size_t)tok[it] * NH + ac[it]);
        }
        float4 g0 = *reinterpret_cast<const float4*>(wgB);
        float4 u0 = *reinterpret_cast<const float4*>(wuB);
#pragma unroll
        for (int it = 0; it < 2; it++) {
            sA[abase[it] + 0]  = f2tf(a0[it].x);
            sA[abase[it] + 4]  = f2tf(a0[it].y);
            sA[abase[it] + 8]  = f2tf(a0[it].z);
            sA[abase[it] + 12] = f2tf(a0[it].w);
        }
        sBg[bbase + 0]  = f2tf(g0.x);  sBg[bbase + 8]  = f2tf(g0.y);
        sBg[bbase + 16] = f2tf(g0.z);  sBg[bbase + 24] = f2tf(g0.w);
        sBu[bbase + 0]  = f2tf(u0.x);  sBu[bbase + 8]  = f2tf(u0.y);
        sBu[bbase + 16] = f2tf(u0.z);  sBu[bbase + 24] = f2tf(u0.w);
    }
    // prefetch A tile 1 into set 1
#pragma unroll
    for (int it = 0; it < 2; it++) {
        pAs[1][it] = make_float4(0.f, 0.f, 0.f, 0.f);
        if (tok[it] >= 0)
            pAs[1][it] = *reinterpret_cast<const float4*>(x + (size_t)tok[it] * NH + BK + ac[it]);
    }
    __syncthreads();

    const int NIT = NH / BK;  // 64
#pragma unroll 2
    for (int k = 0; k < NIT; k++) {
        int buf = k & 1;
        // depth-2 A prefetch: issue LDG for tile k+2 into set (k&1)
        if (k + 2 < NIT) {
            int k0 = (k + 2) * BK;
#pragma unroll
            for (int it = 0; it < 2; it++) {
                pAs[buf][it] = make_float4(0.f, 0.f, 0.f, 0.f);
                if (tok[it] >= 0)
                    pAs[buf][it] = *reinterpret_cast<const float4*>(
                                       x + (size_t)tok[it] * NH + k0 + ac[it]);
            }
        }
        // depth-1 B prefetch: tile k+1
        if (k + 1 < NIT) {
            int k0 = (k + 1) * BK;
            pG = *reinterpret_cast<const float4*>(wgB + (size_t)k0 * NI);
            pU = *reinterpret_cast<const float4*>(wuB + (size_t)k0 * NI);
        }

        unsigned aoff = (unsigned)buf * SA_BUF;
        unsigned boff = (unsigned)buf * SB_BUF;
#pragma unroll
        for (int k8 = 0; k8 < 2; k8++) {
            uint4 a[2];
#pragma unroll
            for (int m = 0; m < 2; m++)
                a[m] = *reinterpret_cast<uint4*>(
                    &sA[aoff + (((unsigned)k8 * 8 + (wm * 2 + m)) * 32 + lane) * 4]);
            uint2 bg[4], bu[4];
#pragma unroll
            for (int n = 0; n < 4; n++) {
                bg[n] = *reinterpret_cast<uint2*>(
                    &sBg[boff + (((unsigned)k8 * 8 + (wn * 4 + n)) * 32 + lane) * 2]);
                bu[n] = *reinterpret_cast<uint2*>(
                    &sBu[boff + (((unsigned)k8 * 8 + (wn * 4 + n)) * 32 + lane) * 2]);
            }
#pragma unroll
            for (int m = 0; m < 2; m++)
#pragma unroll
                for (int n = 0; n < 4; n++) {
                    mma_tf32(dg[m][n], a[m], bg[n]);
                    mma_tf32(du[m][n], a[m], bu[n]);
                }
        }

        if (k + 1 < NIT) {
            int nset = (k + 1) & 1;   // A regs for tile k+1
            __syncthreads();
            unsigned na = (unsigned)(buf ^ 1) * SA_BUF;
            unsigned nb = (unsigned)(buf ^ 1) * SB_BUF;
#pragma unroll
            for (int it = 0; it < 2; it++) {
                sA[na + abase[it] + 0]  = f2tf(pAs[nset][it].x);
                sA[na + abase[it] + 4]  = f2tf(pAs[nset][it].y);
                sA[na + abase[it] + 8]  = f2tf(pAs[nset][it].z);
                sA[na + abase[it] + 12] = f2tf(pAs[nset][it].w);
            }
            sBg[nb + bbase + 0]  = f2tf(pG.x);  sBg[nb + bbase + 8]  = f2tf(pG.y);
            sBg[nb + bbase + 16] = f2tf(pG.z);  sBg[nb + bbase + 24] = f2tf(pG.w);
            sBu[nb + bbase + 0]  = f2tf(pU.x);  sBu[nb + bbase + 8]  = f2tf(pU.y);
            sBu[nb + bbase + 16] = f2tf(pU.z);  sBu[nb + bbase + 24] = f2tf(pU.w);
            __syncthreads();
        }
    }

    // epilogue: silu(g)*u
    size_t base = (size_t)e * MAXP;
    int cg = lane >> 2, ct = lane & 3;
#pragma unroll
    for (int m = 0; m < 2; m++) {
        int rb = row0 + wm * 32 + m * 16 + cg;
#pragma unroll
        for (int n = 0; n < 4; n++) {
            int cb = col0 + wn * 32 + n * 8 + 2 * ct;
            if (rb < cnt) {
                float gv0 = dg[m][n][0], gv1 = dg[m][n][1];
                float s0 = gv0 / (1.f + expf(-gv0));
                float s1 = gv1 / (1.f + expf(-gv1));
                float2 o = make_float2(s0 * du[m][n][0], s1 * du[m][n][1]);
                *reinterpret_cast<float2*>(&g_act[(base + rb) * NI + cb]) = o;
            }
            if (rb + 8 < cnt) {
                float gv2 = dg[m][n][2], gv3 = dg[m][n][3];
                float s2 = gv2 / (1.f + expf(-gv2));
                float s3 = gv3 / (1.f + expf(-gv3));
                float2 o = make_float2(s2 * du[m][n][2], s3 * du[m][n][3]);
                *reinterpret_cast<float2*>(&g_act[(base + rb + 8) * NI + cb]) = o;
            }
        }
    }
}

// ---------------------------------------------------------------------------
// GEMM2 (tf32 TC, depth-2 A prefetch / depth-1 B): pout = wt * (act . w_down)
__global__ __launch_bounds__(256) void gemm2_tc(const float* __restrict__ wd) {
    int e    = blockIdx.z;
    int cnt  = g_cnt[e];
    int row0 = blockIdx.y * BM;
    if (row0 >= cnt) return;
    int col0 = blockIdx.x * BN;

    __shared__ unsigned sA[2 * SA_BUF];   // 16KB
    __shared__ unsigned sB[2 * SB_BUF];   // 8KB

    int tid  = threadIdx.x;
    int lane = tid & 31;
    int wid  = tid >> 5;
    int wm   = wid >> 1;
    int wn   = wid & 1;

    size_t pbase = (size_t)e * MAXP;

    int ac[2];
    bool aval[2];
    unsigned abase[2];
    const float* aptr[2];
#pragma unroll
    for (int it = 0; it < 2; it++) {
        int f = tid + 256 * it;
        int r = f >> 2;
        int c = (f & 3) * 4;
        ac[it] = c;
        aval[it] = (row0 + r) < cnt;
        aptr[it] = &g_act[(pbase + row0 + r) * NI + c];
        int k8  = c >> 3;
        int reg = ((r >> 3) & 1) + 2 * ((c >> 2) & 1);
        abase[it] = (((unsigned)k8 * 8 + (r >> 4)) * 32 + (r & 7) * 4) * 4 + reg;
    }
    int bkr = tid >> 4;
    int bc  = (tid & 15) * 4;
    const float* wdB = wd + (size_t)e * NI * NH + (size_t)bkr * NH + col0 + bc;
    int bk8  = bkr >> 3;
    int bkk  = bkr & 7;
    int breg = bkk >> 2;
    int bt   = bkk & 3;
    int bnt  = bc >> 3;
    unsigned bbase = (((unsigned)bk8 * 8 + bnt) * 32 + (bc & 7) * 4 + bt) * 2 + breg;

    float d[2][4][4] = {};

    float4 pAs[2][2];
    float4 pB;

    // prologue: stage tile 0 directly
    {
        float4 a0[2];
#pragma unroll
        for (int it = 0; it < 2; it++) {
            a0[it] = make_float4(0.f, 0.f, 0.f, 0.f);
            if (aval[it]) a0[it] = *reinterpret_cast<const float4*>(aptr[it]);
        }
        float4 b0 = *reinterpret_cast<const float4*>(wdB);
#pragma unroll
        for (int it = 0; it < 2; it++) {
            sA[abase[it] + 0]  = f2tf(a0[it].x);
            sA[abase[it] + 4]  = f2tf(a0[it].y);
            sA[abase[it] + 8]  = f2tf(a0[it].z);
            sA[abase[it] + 12] = f2tf(a0[it].w);
        }
        sB[bbase + 0]  = f2tf(b0.x);  sB[bbase + 8]  = f2tf(b0.y);
        sB[bbase + 16] = f2tf(b0.z);  sB[bbase + 24] = f2tf(b0.w);
    }
    // prefetch A tile 1 into set 1
#pragma unroll
    for (int it = 0; it < 2; it++) {
        pAs[1][it] = make_float4(0.f, 0.f, 0.f, 0.f);
        if (aval[it]) pAs[1][it] = *reinterpret_cast<const float4*>(aptr[it] + BK);
    }
    __syncthreads();

    const int NIT = NI / BK;  // 32
#pragma unroll 2
    for (int k = 0; k < NIT; k++) {
        int buf = k & 1;
        if (k + 2 < NIT) {
            int k0 = (k + 2) * BK;
#pragma unroll
            for (int it = 0; it < 2; it++) {
                pAs[buf][it] = make_float4(0.f, 0.f, 0.f, 0.f);
                if (aval[it])
                    pAs[buf][it] = *reinterpret_cast<const float4*>(aptr[it] + k0);
            }
        }
        if (k + 1 < NIT) {
            int k0 = (k + 1) * BK;
            pB = *reinterpret_cast<const float4*>(wdB + (size_t)k0 * NH);
        }

        unsigned aoff = (unsigned)buf * SA_BUF;
        unsigned boff = (unsigned)buf * SB_BUF;
#pragma unroll
        for (int k8 = 0; k8 < 2; k8++) {
            uint4 a[2];
#pragma unroll
            for (int m = 0; m < 2; m++)
                a[m] = *reinterpret_cast<uint4*>(
                    &sA[aoff + (((unsigned)k8 * 8 + (wm * 2 + m)) * 32 + lane) * 4]);
            uint2 b[4];
#pragma unroll
            for (int n = 0; n < 4; n++)
                b[n] = *reinterpret_cast<uint2*>(
                    &sB[boff + (((unsigned)k8 * 8 + (wn * 4 + n)) * 32 + lane) * 2]);
#pragma unroll
            for (int m = 0; m < 2; m++)
#pragma unroll
                for (int n = 0; n < 4; n++)
                    mma_tf32(d[m][n], a[m], b[n]);
        }

        if (k + 1 < NIT) {
            int nset = (k + 1) & 1;
            __syncthreads();
            unsigned na = (unsigned)(buf ^ 1) * SA_BUF;
            unsigned nb = (unsigned)(buf ^ 1) * SB_BUF;
#pragma unroll
            for (int it = 0; it < 2; it++) {
                sA[na + abase[it] + 0]  = f2tf(pAs[nset][it].x);
                sA[na + abase[it] + 4]  = f2tf(pAs[nset][it].y);
                sA[na + abase[it] + 8]  = f2tf(pAs[nset][it].z);
                sA[na + abase[it] + 12] = f2tf(pAs[nset][it].w);
            }
            sB[nb + bbase + 0]  = f2tf(pB.x);  sB[nb + bbase + 8]  = f2tf(pB.y);
            sB[nb + bbase + 16] = f2tf(pB.z);  sB[nb + bbase + 24] = f2tf(pB.w);
            __syncthreads();
        }
    }

    int cg = lane >> 2, ct = lane & 3;
#pragma unroll
    for (int m = 0; m < 2; m++) {
        int rb = row0 + wm * 32 + m * 16 + cg;
        float w0 = (rb     < cnt) ? g_wt[e * MAXP + rb]     : 0.f;
        float w1 = (rb + 8 < cnt) ? g_wt[e * MAXP + rb + 8] : 0.f;
#pragma unroll
        for (int n = 0; n < 4; n++) {
            int cb = col0 + wn * 32 + n * 8 + 2 * ct;
            if (rb < cnt) {
                float2 o = make_float2(d[m][n][0] * w0, d[m][n][1] * w0);
                *reinterpret_cast<float2*>(&g_pout[(pbase + rb) * NH + cb]) = o;
            }
            if (rb + 8 < cnt) {
                float2 o = make_float2(d[m][n][2] * w1, d[m][n][3] * w1);
                *reinterpret_cast<float2*>(&g_pout[(pbase + rb + 8) * NH + cb]) = o;
            }
        }
    }
}

// ---------------------------------------------------------------------------
// Combine (vectorized): out[t] += sum over this token's pairs (topk order).
// 256 threads/block, one float4 per thread (NH/4 == 256).
__global__ void combine_kernel(float* __restrict__ out) {
    int t  = blockIdx.x;
    int np = g_tk_n[t];
    int p[TOPK];
    for (int j = 0; j < np; j++) p[j] = g_tk_pair[t * TOPK + j];
    int h4 = threadIdx.x;      // 0..255 -> float4 index
    float4 s = *reinterpret_cast<float4*>(&out[(size_t)t * NH + h4 * 4]);
    for (int j = 0; j < np; j++) {
        float4 v = *reinterpret_cast<const float4*>(&g_pout[(size_t)p[j] * NH + h4 * 4]);
        s.x += v.x; s.y += v.y; s.z += v.z; s.w += v.w;
    }
    *reinterpret_cast<float4*>(&out[(size_t)t * NH + h4 * 4]) = s;
}

// ---------------------------------------------------------------------------
extern "C" void kernel_launch(void* const* d_in, const int* in_sizes, int n_in,
                              void* d_out, int out_size) {
    (void)in_sizes; (void)n_in; (void)out_size;
    const float* x    = (const float*)d_in[0];
    const float* rw   = (const float*)d_in[1];
    const float* bias = (const float*)d_in[2];
    const float* wg   = (const float*)d_in[3];
    const float* wu   = (const float*)d_in[4];
    const float* wd   = (const float*)d_in[5];
    float* out = (float*)d_out;

    reset_kernel<<<1, 32>>>();
    router_kernel<<<T_TOK, 256>>>(x, rw, bias, out);

    dim3 g1(NI / BN, MAXP / BM, NE);
    gemm1_tc<<<g1, 256>>>(x, wg, wu);

    dim3 g2(NH / BN, MAXP / BM, NE);
    gemm2_tc<<<g2, 256>>>(wd);

    combine_kernel<<<T_TOK, 256>>>(out);
}

// round 9
// speedup vs baseline: 2.6480x; 2.6480x over previous
#include <cuda_runtime.h>
#include <math.h>

#define T_TOK 4096
#define NH 1024          // hidden
#define NI 512           // intermediate
#define NE 16            // real experts
#define NSLOT 32         // real + zero slots
#define TOPK 4
#define MAXP 4096        // max pairs per expert (<= T)

#define BM 128
#define BN 64
#define BK 16

// ---- static device scratch (no runtime allocation allowed) ----
__device__ int   g_cnt[NE];
__device__ int   g_tok[NE * MAXP];
__device__ float g_wt [NE * MAXP];
__device__ int   g_tk_n[T_TOK];
__device__ int   g_tk_pair[T_TOK * TOPK];
__device__ float g_act [(size_t)NE * MAXP * NI];
__device__ float g_pout[(size_t)NE * MAXP * NH];

// ---------------------------------------------------------------------------
__device__ __forceinline__ void mma_tf32u(float* d, const unsigned* a,
                                          unsigned b0, unsigned b1) {
    asm volatile(
        "mma.sync.aligned.m16n8k8.row.col.f32.tf32.tf32.f32 "
        "{%0,%1,%2,%3}, {%4,%5,%6,%7}, {%8,%9}, {%0,%1,%2,%3};"
        : "+f"(d[0]), "+f"(d[1]), "+f"(d[2]), "+f"(d[3])
        : "r"(a[0]), "r"(a[1]), "r"(a[2]), "r"(a[3]), "r"(b0), "r"(b1));
}

#define CPA(dst, src, sz) \
    asm volatile("cp.async.cg.shared.global [%0], [%1], 16, %2;" \
                 :: "r"(dst), "l"(src), "r"(sz))
#define CPC() asm volatile("cp.async.commit_group;")
#define CPW(n) asm volatile("cp.async.wait_group %0;" :: "n"(n))

__device__ __forceinline__ unsigned sptr(const void* p) {
    return (unsigned)__cvta_generic_to_shared(p);
}
__device__ __forceinline__ unsigned fau(float f) { return __float_as_uint(f); }

// ---------------------------------------------------------------------------
__global__ void reset_kernel() {
    int i = threadIdx.x;
    if (i < NE) g_cnt[i] = 0;
}

// ---------------------------------------------------------------------------
// Router: one block (256 threads) per token.
__global__ void router_kernel(const float* __restrict__ x,
                              const float* __restrict__ rw,
                              const float* __restrict__ bias,
                              float* __restrict__ out) {
    int t = blockIdx.x;
    __shared__ float sc[NSLOT];
    __shared__ float s_zero;
    int tid  = threadIdx.x;
    int slot = tid >> 3;
    int sub  = tid & 7;
    const float* xr = x  + (size_t)t * NH;
    const float* wr = rw + (size_t)slot * NH;

    float acc = 0.f;
    for (int h = sub * 4; h < NH; h += 32) {
        float4 xv = *reinterpret_cast<const float4*>(xr + h);
        float4 wv = *reinterpret_cast<const float4*>(wr + h);
        acc += xv.x * wv.x + xv.y * wv.y + xv.z * wv.z + xv.w * wv.w;
    }
    acc += __shfl_down_sync(0xffffffffu, acc, 4, 8);
    acc += __shfl_down_sync(0xffffffffu, acc, 2, 8);
    acc += __shfl_down_sync(0xffffffffu, acc, 1, 8);
    if (sub == 0) sc[slot] = acc;
    __syncthreads();

    if (tid == 0) {
        float mx = -1e30f;
        for (int i = 0; i < NSLOT; i++) mx = fmaxf(mx, sc[i]);
        float e[NSLOT], sum = 0.f;
        for (int i = 0; i < NSLOT; i++) { e[i] = expf(sc[i] - mx); sum += e[i]; }
        float inv = 1.f / sum;
        float sb[NSLOT];
        for (int i = 0; i < NSLOT; i++) {
            sc[i] = e[i] * inv;
            sb[i] = sc[i] + bias[i];
        }
        float zero_w = 0.f;
        int tkn = 0;
        for (int kk = 0; kk < TOPK; kk++) {
            int bi = 0; float bv = -1e30f;
            for (int i = 0; i < NSLOT; i++)
                if (sb[i] > bv) { bv = sb[i]; bi = i; }
            sb[bi] = -1e30f;
            float w = sc[bi];
            if (bi < NE) {
                int s2 = atomicAdd(&g_cnt[bi], 1);
                g_tok[bi * MAXP + s2] = t;
                g_wt [bi * MAXP + s2] = w;
                g_tk_pair[t * TOPK + tkn] = bi * MAXP + s2;
                tkn++;
            } else {
                zero_w += w;
            }
        }
        g_tk_n[t] = tkn;
        s_zero = zero_w;
    }
    __syncthreads();

    float zw = s_zero;
    for (int h = tid; h < NH; h += 256)
        out[(size_t)t * NH + h] = zw * xr[h];
}

// ---------------------------------------------------------------------------
// Smem layouts (per stage):
//   A tile: 128 rows x 16 k, word(r,k) = r*16 + (k ^ (((r>>1)&3)<<2))   (8KB)
//   B tile:  16 k  x 64 n,  word(k,n) = k*64 + (n ^ ((k&7)<<3))         (4KB)
// Both cp.async writes and fragment LDS.32 reads are bank-conflict-free.

// ---------------------------------------------------------------------------
// GEMM1: act = silu(X.Wg)*(X.Wu).  Block 128x64, 8 warps (4m x 2n),
// warp tile 32x32 per matrix.  3-stage cp.async pipeline, 48KB smem.
__global__ __launch_bounds__(256) void gemm1_tc(const float* __restrict__ x,
                                                const float* __restrict__ wg,
                                                const float* __restrict__ wu) {
    int e    = blockIdx.z;
    int cnt  = g_cnt[e];
    int row0 = blockIdx.y * BM;
    if (row0 >= cnt) return;
    int col0 = blockIdx.x * BN;

    __shared__ float sA [3][BM * BK];    // 3 x 8KB
    __shared__ float sBg[3][BK * BN];    // 3 x 4KB
    __shared__ float sBu[3][BK * BN];    // 3 x 4KB

    int tid  = threadIdx.x;
    int lane = tid & 31;
    int wid  = tid >> 5;
    int wm   = wid >> 1;      // 0..3
    int wn   = wid & 1;       // 0..1

    // --- A loader: 2 chunks/thread ---
    int tok[2], lc[2];
    unsigned adst[2];
#pragma unroll
    for (int it = 0; it < 2; it++) {
        int f = tid + 256 * it;
        int r = f >> 2;
        int c = (f & 3) * 4;
        lc[it] = c;
        int rr = row0 + r;
        tok[it] = (rr < cnt) ? g_tok[e * MAXP + rr] : -1;
        adst[it] = r * 16 + (c ^ (((r >> 1) & 3) << 2));
    }
    // --- B loader: 1 chunk/thread per matrix ---
    int bkr = tid >> 4;             // 0..15
    int bnc = (tid & 15) * 4;       // 0..60
    unsigned bdst = bkr * 64 + (bnc ^ ((bkr & 7) << 3));
    const float* wgP = wg + (size_t)e * NH * NI + (size_t)bkr * NI + col0 + bnc;
    const float* wuP = wu + (size_t)e * NH * NI + (size_t)bkr * NI + col0 + bnc;

    float dg[2][4][4] = {};
    float du[2][4][4] = {};

    const int NIT = NH / BK;  // 64

    // prologue: stages 0,1
#pragma unroll
    for (int s = 0; s < 2; s++) {
        int kb = s * BK;
#pragma unroll
        for (int it = 0; it < 2; it++) {
            const float* src = (tok[it] >= 0)
                ? x + (size_t)tok[it] * NH + kb + lc[it] : x;
            CPA(sptr(&sA[s][adst[it]]), src, tok[it] >= 0 ? 16 : 0);
        }
        CPA(sptr(&sBg[s][bdst]), wgP + (size_t)kb * NI, 16);
        CPA(sptr(&sBu[s][bdst]), wuP + (size_t)kb * NI, 16);
        CPC();
    }

    // per-thread fragment address constants
    int swA = ((lane >> 3) & 3) << 2;
    int ar  = lane >> 2;
    int akk = lane & 3;
    int swB = (lane & 3) << 3;
    int bn0 = lane >> 2;

    int buf = 0;
    for (int kt = 0; kt < NIT; kt++) {
        CPW(1);
        __syncthreads();

        const float* A  = sA [buf];
        const float* Bg = sBg[buf];
        const float* Bu = sBu[buf];
#pragma unroll
        for (int k8 = 0; k8 < 2; k8++) {
            int ka  = (k8 * 8 + akk)     ^ swA;
            int ka4 = (k8 * 8 + akk + 4) ^ swA;
            unsigned a[2][4];
#pragma unroll
            for (int m = 0; m < 2; m++) {
                int rb = (wm * 32 + m * 16 + ar) * 16;
                a[m][0] = fau(A[rb + ka]);
                a[m][1] = fau(A[rb + 128 + ka]);
                a[m][2] = fau(A[rb + ka4]);
                a[m][3] = fau(A[rb + 128 + ka4]);
            }
            int kr0 = (k8 * 8 + akk) * 64;
            int kr4 = kr0 + 4 * 64;
#pragma unroll
            for (int nt = 0; nt < 4; nt++) {
                int nb = wn * 32 + nt * 8 + bn0;
                unsigned g0 = fau(Bg[kr0 + (nb ^ swB)]);
                unsigned g1 = fau(Bg[kr4 + (nb ^ swB ^ 32)]);
                unsigned u0 = fau(Bu[kr0 + (nb ^ swB)]);
                unsigned u1 = fau(Bu[kr4 + (nb ^ swB ^ 32)]);
#pragma unroll
                for (int m = 0; m < 2; m++) {
                    mma_tf32u(dg[m][nt], a[m], g0, g1);
                    mma_tf32u(du[m][nt], a[m], u0, u1);
                }
            }
        }

        // issue stage kt+2 into buffer (kt+2)%3 (== buffer used at kt-1; all
        // warps are past this iter's syncthreads, so it is free)
        int kn = kt + 2;
        if (kn < NIT) {
            int s  = (buf + 2 >= 3) ? buf - 1 : buf + 2;
            int kb = kn * BK;
#pragma unroll
            for (int it = 0; it < 2; it++) {
                const float* src = (tok[it] >= 0)
                    ? x + (size_t)tok[it] * NH + kb + lc[it] : x;
                CPA(sptr(&sA[s][adst[it]]), src, tok[it] >= 0 ? 16 : 0);
            }
            CPA(sptr(&sBg[s][bdst]), wgP + (size_t)kb * NI, 16);
            CPA(sptr(&sBu[s][bdst]), wuP + (size_t)kb * NI, 16);
        }
        CPC();   // empty group when kn >= NIT keeps wait arithmetic uniform
        if (++buf == 3) buf = 0;
    }

    // epilogue: silu(g)*u
    size_t base = (size_t)e * MAXP;
    int cg = lane >> 2, ct = lane & 3;
#pragma unroll
    for (int m = 0; m < 2; m++) {
        int rb = row0 + wm * 32 + m * 16 + cg;
#pragma unroll
        for (int n = 0; n < 4; n++) {
            int cb = col0 + wn * 32 + n * 8 + 2 * ct;
            if (rb < cnt) {
                float gv0 = dg[m][n][0], gv1 = dg[m][n][1];
                float s0 = gv0 / (1.f + expf(-gv0));
                float s1 = gv1 / (1.f + expf(-gv1));
                float2 o = make_float2(s0 * du[m][n][0], s1 * du[m][n][1]);
                *reinterpret_cast<float2*>(&g_act[(base + rb) * NI + cb]) = o;
            }
            if (rb + 8 < cnt) {
                float gv2 = dg[m][n][2], gv3 = dg[m][n][3];
                float s2 = gv2 / (1.f + expf(-gv2));
                float s3 = gv3 / (1.f + expf(-gv3));
                float2 o = make_float2(s2 * du[m][n][2], s3 * du[m][n][3]);
                *reinterpret_cast<float2*>(&g_act[(base + rb + 8) * NI + cb]) = o;
            }
        }
    }
}

// ---------------------------------------------------------------------------
// GEMM2: pout = wt * (act . w_down).  Block 128x64, 4-stage pipeline (48KB).
__global__ __launch_bounds__(256) void gemm2_tc(const float* __restrict__ wd) {
    int e    = blockIdx.z;
    int cnt  = g_cnt[e];
    int row0 = blockIdx.y * BM;
    if (row0 >= cnt) return;
    int col0 = blockIdx.x * BN;

    __shared__ float sA[4][BM * BK];    // 4 x 8KB
    __shared__ float sB[4][BK * BN];    // 4 x 4KB

    int tid  = threadIdx.x;
    int lane = tid & 31;
    int wid  = tid >> 5;
    int wm   = wid >> 1;
    int wn   = wid & 1;

    size_t pbase = (size_t)e * MAXP;

    int lc[2];
    bool aval[2];
    unsigned adst[2];
    const float* aptr[2];
#pragma unroll
    for (int it = 0; it < 2; it++) {
        int f = tid + 256 * it;
        int r = f >> 2;
        int c = (f & 3) * 4;
        lc[it] = c;
        aval[it] = (row0 + r) < cnt;
        aptr[it] = &g_act[(pbase + row0 + r) * NI + c];
        adst[it] = r * 16 + (c ^ (((r >> 1) & 3) << 2));
    }
    int bkr = tid >> 4;
    int bnc = (tid & 15) * 4;
    unsigned bdst = bkr * 64 + (bnc ^ ((bkr & 7) << 3));
    const float* wdP = wd + (size_t)e * NI * NH + (size_t)bkr * NH + col0 + bnc;

    float d[2][4][4] = {};

    const int NIT = NI / BK;  // 32

    // prologue: stages 0..2
#pragma unroll
    for (int s = 0; s < 3; s++) {
        int kb = s * BK;
#pragma unroll
        for (int it = 0; it < 2; it++) {
            const float* src = aval[it] ? aptr[it] + kb : &g_act[0];
            CPA(sptr(&sA[s][adst[it]]), src, aval[it] ? 16 : 0);
        }
        CPA(sptr(&sB[s][bdst]), wdP + (size_t)kb * NH, 16);
        CPC();
    }

    int swA = ((lane >> 3) & 3) << 2;
    int ar  = lane >> 2;
    int akk = lane & 3;
    int swB = (lane & 3) << 3;
    int bn0 = lane >> 2;

    int buf = 0;
    for (int kt = 0; kt < NIT; kt++) {
        CPW(2);
        __syncthreads();

        const float* A = sA[buf];
        const float* B = sB[buf];
#pragma unroll
        for (int k8 = 0; k8 < 2; k8++) {
            int ka  = (k8 * 8 + akk)     ^ swA;
            int ka4 = (k8 * 8 + akk + 4) ^ swA;
            unsigned a[2][4];
#pragma unroll
            for (int m = 0; m < 2; m++) {
                int rb = (wm * 32 + m * 16 + ar) * 16;
                a[m][0] = fau(A[rb + ka]);
                a[m][1] = fau(A[rb + 128 + ka]);
                a[m][2] = fau(A[rb + ka4]);
                a[m][3] = fau(A[rb + 128 + ka4]);
            }
            int kr0 = (k8 * 8 + akk) * 64;
            int kr4 = kr0 + 4 * 64;
#pragma unroll
            for (int nt = 0; nt < 4; nt++) {
                int nb = wn * 32 + nt * 8 + bn0;
                unsigned b0 = fau(B[kr0 + (nb ^ swB)]);
                unsigned b1 = fau(B[kr4 + (nb ^ swB ^ 32)]);
#pragma unroll
                for (int m = 0; m < 2; m++)
                    mma_tf32u(d[m][nt], a[m], b0, b1);
            }
        }

        int kn = kt + 3;
        if (kn < NIT) {
            int s  = buf + 3 >= 4 ? buf - 1 : buf + 3;
            int kb = kn * BK;
#pragma unroll
            for (int it = 0; it < 2; it++) {
                const float* src = aval[it] ? aptr[it] + kb : &g_act[0];
                CPA(sptr(&sA[s][adst[it]]), src, aval[it] ? 16 : 0);
            }
            CPA(sptr(&sB[s][bdst]), wdP + (size_t)kb * NH, 16);
        }
        CPC();
        buf = (buf + 1) & 3;
    }

    int cg = lane >> 2, ct = lane & 3;
#pragma unroll
    for (int m = 0; m < 2; m++) {
        int rb = row0 + wm * 32 + m * 16 + cg;
        float w0 = (rb     < cnt) ? g_wt[e * MAXP + rb]     : 0.f;
        float w1 = (rb + 8 < cnt) ? g_wt[e * MAXP + rb + 8] : 0.f;
#pragma unroll
        for (int n = 0; n < 4; n++) {
            int cb = col0 + wn * 32 + n * 8 + 2 * ct;
            if (rb < cnt) {
                float2 o = make_float2(d[m][n][0] * w0, d[m][n][1] * w0);
                *reinterpret_cast<float2*>(&g_pout[(pbase + rb) * NH + cb]) = o;
            }
            if (rb + 8 < cnt) {
                float2 o = make_float2(d[m][n][2] * w1, d[m][n][3] * w1);
                *reinterpret_cast<float2*>(&g_pout[(pbase + rb + 8) * NH + cb]) = o;
            }
        }
    }
}

// ---------------------------------------------------------------------------
// Combine (vectorized): out[t] += sum over this token's pairs (topk order).
__global__ void combine_kernel(float* __restrict__ out) {
    int t  = blockIdx.x;
    int np = g_tk_n[t];
    int p[TOPK];
    for (int j = 0; j < np; j++) p[j] = g_tk_pair[t * TOPK + j];
    int h4 = threadIdx.x;
    float4 s = *reinterpret_cast<float4*>(&out[(size_t)t * NH + h4 * 4]);
    for (int j = 0; j < np; j++) {
        float4 v = *reinterpret_cast<const float4*>(&g_pout[(size_t)p[j] * NH + h4 * 4]);
        s.x += v.x; s.y += v.y; s.z += v.z; s.w += v.w;
    }
    *reinterpret_cast<float4*>(&out[(size_t)t * NH + h4 * 4]) = s;
}

// ---------------------------------------------------------------------------
extern "C" void kernel_launch(void* const* d_in, const int* in_sizes, int n_in,
                              void* d_out, int out_size) {
    (void)in_sizes; (void)n_in; (void)out_size;
    const float* x    = (const float*)d_in[0];
    const float* rw   = (const float*)d_in[1];
    const float* bias = (const float*)d_in[2];
    const float* wg   = (const float*)d_in[3];
    const float* wu   = (const float*)d_in[4];
    const float* wd   = (const float*)d_in[5];
    float* out = (float*)d_out;

    reset_kernel<<<1, 32>>>();
    router_kernel<<<T_TOK, 256>>>(x, rw, bias, out);

    dim3 g1(NI / BN, MAXP / BM, NE);
    gemm1_tc<<<g1, 256>>>(x, wg, wu);

    dim3 g2(NH / BN, MAXP / BM, NE);
    gemm2_tc<<<g2, 256>>>(wd);

    combine_kernel<<<T_TOK, 256>>>(out);
}